// round 10
// baseline (speedup 1.0000x reference)
#include <cuda_runtime.h>
#include <cstddef>

#define N_NODES 100000
#define N_EDGES 600000
#define FEAT    128
#define NCHS    ((N_NODES + 1023) / 1024)   // scan chunks: 98

// ---------------- scratch (device globals; no allocation allowed) ----------
__device__ __align__(128) float g_bufA[(size_t)N_NODES * FEAT];
__device__ __align__(128) float g_bufB[(size_t)N_NODES * FEAT];
__device__ __align__(128) float g_hn  [(size_t)N_NODES * FEAT];
__device__ int g_deg[N_NODES];
__device__ int g_rowptr[N_NODES + 1];
__device__ int g_cursor[N_NODES];
__device__ int g_csr[N_EDGES];
__device__ int g_blocksum[NCHS];
__device__ int g_blockoff[NCHS];

#define BUF_EXT 0
#define BUF_A   1
#define BUF_B   2

__device__ __forceinline__ const float* sel_src(int sel, const float* ext) {
    if (sel == BUF_A) return g_bufA;
    if (sel == BUF_B) return g_bufB;
    return ext;
}
__device__ __forceinline__ float* sel_dst(int sel, float* ext) {
    if (sel == BUF_A) return g_bufA;
    if (sel == BUF_B) return g_bufB;
    return ext;
}

// ---------------- small helpers -------------------------------------------
__device__ __forceinline__ unsigned long long pack2(float a, float b) {
    unsigned long long r;
    asm("mov.b64 %0, {%1,%2};" : "=l"(r) : "f"(a), "f"(b));
    return r;
}
__device__ __forceinline__ void ffma2(unsigned long long& d,
                                      unsigned long long a,
                                      unsigned long long b) {
    asm("fma.rn.f32x2 %0, %1, %2, %0;" : "+l"(d) : "l"(a), "l"(b));
}

// ---------------- CSR construction ----------------------------------------
__global__ void k_zero_deg() {
    int i = blockIdx.x * blockDim.x + threadIdx.x;
    if (i < N_NODES) g_deg[i] = 0;
}
__global__ void k_count(const int* __restrict__ dst) {
    int e = blockIdx.x * blockDim.x + threadIdx.x;
    if (e < N_EDGES) atomicAdd(&g_deg[dst[e]], 1);
}
__global__ __launch_bounds__(1024) void k_scan1() {
    __shared__ int sh[1024];
    int tid = threadIdx.x;
    int i = blockIdx.x * 1024 + tid;
    int v = (i < N_NODES) ? g_deg[i] : 0;
    sh[tid] = v;
    __syncthreads();
#pragma unroll
    for (int off = 1; off < 1024; off <<= 1) {
        int t = (tid >= off) ? sh[tid - off] : 0;
        __syncthreads();
        sh[tid] += t;
        __syncthreads();
    }
    if (i < N_NODES) g_rowptr[i] = sh[tid] - v;
    if (tid == 1023) g_blocksum[blockIdx.x] = sh[1023];
}
__global__ void k_scan2() {
    __shared__ int sh[128];
    int tid = threadIdx.x;
    int v = (tid < NCHS) ? g_blocksum[tid] : 0;
    sh[tid] = v;
    __syncthreads();
#pragma unroll
    for (int off = 1; off < 128; off <<= 1) {
        int t = (tid >= off) ? sh[tid - off] : 0;
        __syncthreads();
        sh[tid] += t;
        __syncthreads();
    }
    if (tid < NCHS) g_blockoff[tid] = sh[tid] - v;
    if (tid == NCHS - 1) g_rowptr[N_NODES] = sh[tid];
}
__global__ void k_scan3() {
    int i = blockIdx.x * blockDim.x + threadIdx.x;
    if (i < N_NODES) {
        int r = g_rowptr[i] + g_blockoff[i >> 10];
        g_rowptr[i] = r;
        g_cursor[i] = r;
    }
}
__global__ void k_fill(const int* __restrict__ src, const int* __restrict__ dst) {
    int e = blockIdx.x * blockDim.x + threadIdx.x;
    if (e < N_EDGES) {
        int p = atomicAdd(&g_cursor[dst[e]], 1);
        g_csr[p] = src[e];
    }
}

// ---------------- neighbor mean aggregation (warp per node) ----------------
__global__ void k_aggregate(int h_sel, const float* __restrict__ h_ext) {
    const float* __restrict__ h = sel_src(h_sel, h_ext);
    int node = (blockIdx.x * blockDim.x + threadIdx.x) >> 5;
    if (node >= N_NODES) return;
    int lane = threadIdx.x & 31;
    int beg = g_rowptr[node], end = g_rowptr[node + 1];
    float4 acc = make_float4(0.f, 0.f, 0.f, 0.f);
    for (int e = beg; e < end; e++) {
        int s = g_csr[e];
        float4 v = ((const float4*)(h + (size_t)s * FEAT))[lane];
        acc.x += v.x; acc.y += v.y; acc.z += v.z; acc.w += v.w;
    }
    float inv = 1.0f / fmaxf((float)(end - beg), 1.0f);
    acc.x *= inv; acc.y *= inv; acc.z *= inv; acc.w *= inv;
    ((float4*)(g_hn + (size_t)node * FEAT))[lane] = acc;
}

// ---------------- fused (dual-)GEMM + bias (+ReLU), double-buffered --------
// C[M,N] = act( A1@B1 (+ hn@B2) + bias1 (+ bias2) )
// B matrices are [K, N] row-major. Requires BN == N.
// b-fragments are interleaved: thread tx owns NGRP float4 column groups at
// g*GS + tx*4 -> conflict-free LDS (16 lanes read consecutive 16B chunks).
template <int KTOT, int N, int BM, int BN, int BK, int TM, int TN, bool DUAL, bool RELU>
__global__ __launch_bounds__(256)
void k_gemm(int a1_sel, const float* __restrict__ A1_ext,
            const float* __restrict__ B1, const float* __restrict__ B2,
            const float* __restrict__ bias1, const float* __restrict__ bias2,
            int c_sel, float* __restrict__ C_ext, int M) {
    constexpr int K    = DUAL ? KTOT / 2 : KTOT;
    constexpr int TX   = BN / TN;                 // 16
    constexpr int TY   = BM / TM;                 // 16
    constexpr int NT   = KTOT / BK;               // outer iterations
    constexpr int LA   = (BM * BK / 4) / 256;     // A float4 loads/thread
    constexpr int LB   = (BK * BN / 4) / 256;     // B float4 loads/thread
    constexpr int NGRP = TN / 4;                  // column groups per thread
    constexpr int GS   = BN / NGRP;               // group stride (columns)
    static_assert(TX * TY == 256, "thread count mismatch");
    static_assert(BN == N, "BN must equal N");
    static_assert(K % BK == 0 && LA >= 1 && LB >= 1, "tiling");

    const float* __restrict__ A1 = sel_src(a1_sel, A1_ext);
    float* __restrict__ C = sel_dst(c_sel, C_ext);

    __shared__ __align__(16) float As[2][BK * BM];   // As[buf][k][m]
    __shared__ __align__(16) float Bs[2][BK * BN];   // Bs[buf][k][n]

    const int tid = threadIdx.x;
    const int tx = tid % TX, ty = tid / TX;
    const int row0 = blockIdx.x * BM;

    unsigned long long acc[TM][TN / 2];
#pragma unroll
    for (int m = 0; m < TM; m++)
#pragma unroll
        for (int j = 0; j < TN / 2; j++) acc[m][j] = 0ull;

    float4 ra[LA], rb[LB];

    // fetch tile `it` into registers
    auto fetch = [&](int it, float4* fa, float4* fb) {
        const bool first = (!DUAL) || (it * BK < K);
        const float* __restrict__ A = first ? A1 : (const float*)g_hn;
        const float* __restrict__ B = first ? B1 : B2;
        const int ka = first ? it * BK : it * BK - K;
#pragma unroll
        for (int i = 0; i < LA; i++) {
            int idx = i * 256 + tid;
            int kq = idx & 3, row = idx >> 2;
            fa[i] = make_float4(0.f, 0.f, 0.f, 0.f);
            if (row0 + row < M)
                fa[i] = *(const float4*)(A + (size_t)(row0 + row) * K + ka + kq * 4);
        }
#pragma unroll
        for (int i = 0; i < LB; i++) {
            int idx = i * 256 + tid;
            int kr = idx / (BN / 4), n4 = idx % (BN / 4);
            fb[i] = *(const float4*)(B + (size_t)(ka + kr) * N + n4 * 4);
        }
    };
    // stash register tile into smem buffer `buf`
    auto stash = [&](int buf, const float4* fa, const float4* fb) {
#pragma unroll
        for (int i = 0; i < LA; i++) {
            int idx = i * 256 + tid;
            int kq = idx & 3, row = idx >> 2;
            As[buf][(kq * 4 + 0) * BM + row] = fa[i].x;
            As[buf][(kq * 4 + 1) * BM + row] = fa[i].y;
            As[buf][(kq * 4 + 2) * BM + row] = fa[i].z;
            As[buf][(kq * 4 + 3) * BM + row] = fa[i].w;
        }
#pragma unroll
        for (int i = 0; i < LB; i++)
            ((float4*)Bs[buf])[i * 256 + tid] = fb[i];
    };

    fetch(0, ra, rb);
    stash(0, ra, rb);
    __syncthreads();

#pragma unroll 1
    for (int it = 0; it < NT; it++) {
        const int cur = it & 1;
        float4 ra2[LA], rb2[LB];
        if (it + 1 < NT) fetch(it + 1, ra2, rb2);   // LDG overlaps compute

#pragma unroll
        for (int k = 0; k < BK; k++) {
            unsigned long long ap[TM];
#pragma unroll
            for (int q = 0; q < TM / 4; q++) {
                float4 a4 = *(const float4*)&As[cur][k * BM + ty * TM + 4 * q];
                ap[4 * q + 0] = pack2(a4.x, a4.x);
                ap[4 * q + 1] = pack2(a4.y, a4.y);
                ap[4 * q + 2] = pack2(a4.z, a4.z);
                ap[4 * q + 3] = pack2(a4.w, a4.w);
            }
            unsigned long long bp[TN / 2];
#pragma unroll
            for (int g = 0; g < NGRP; g++) {
                ulonglong2 t =
                    *(const ulonglong2*)&Bs[cur][k * BN + g * GS + tx * 4];
                bp[2 * g + 0] = t.x;
                bp[2 * g + 1] = t.y;
            }
#pragma unroll
            for (int m = 0; m < TM; m++)
#pragma unroll
                for (int j = 0; j < TN / 2; j++)
                    ffma2(acc[m][j], ap[m], bp[j]);
        }

        if (it + 1 < NT) {
            stash(cur ^ 1, ra2, rb2);
            __syncthreads();
        }
    }

    // epilogue: bias (+relu), float4 stores per column group
    float bs[TN];
#pragma unroll
    for (int g = 0; g < NGRP; g++)
#pragma unroll
        for (int t = 0; t < 4; t++) {
            int col = g * GS + tx * 4 + t;
            bs[g * 4 + t] = bias1[col] + (DUAL ? bias2[col] : 0.0f);
        }
#pragma unroll
    for (int m = 0; m < TM; m++) {
        int grow = row0 + ty * TM + m;
        if (grow < M) {
#pragma unroll
            for (int g = 0; g < NGRP; g++) {
                union { unsigned long long u; float2 f; } c0, c1;
                c0.u = acc[m][2 * g];
                c1.u = acc[m][2 * g + 1];
                float4 o;
                o.x = c0.f.x + bs[g * 4 + 0];
                o.y = c0.f.y + bs[g * 4 + 1];
                o.z = c1.f.x + bs[g * 4 + 2];
                o.w = c1.f.y + bs[g * 4 + 3];
                if (RELU) {
                    o.x = fmaxf(o.x, 0.f); o.y = fmaxf(o.y, 0.f);
                    o.z = fmaxf(o.z, 0.f); o.w = fmaxf(o.w, 0.f);
                }
                *(float4*)(C + (size_t)grow * N + g * GS + tx * 4) = o;
            }
        }
    }
}

// ---------------- launch ----------------------------------------------------
extern "C" void kernel_launch(void* const* d_in, const int* in_sizes, int n_in,
                              void* d_out, int out_size) {
    const float* feat = (const float*)d_in[0];
    const int*   src  = (const int*)d_in[1];
    const int*   dst  = (const int*)d_in[2];
    const float* Ws0 = (const float*)d_in[3];  const float* bs0 = (const float*)d_in[4];
    const float* Wn0 = (const float*)d_in[5];  const float* bn0 = (const float*)d_in[6];
    const float* Ws1 = (const float*)d_in[7];  const float* bs1 = (const float*)d_in[8];
    const float* Wn1 = (const float*)d_in[9];  const float* bn1 = (const float*)d_in[10];
    const float* Ws2 = (const float*)d_in[11]; const float* bs2 = (const float*)d_in[12];
    const float* Wn2 = (const float*)d_in[13]; const float* bn2 = (const float*)d_in[14];
    const float* Wout = (const float*)d_in[15]; const float* bout = (const float*)d_in[16];
    float* out = (float*)d_out;

    const int ZB = (N_NODES + 255) / 256;
    const int EB = (N_EDGES + 255) / 256;
    const int AGG_B  = (N_NODES + 7) / 8;
    const int GEMM_B = (N_NODES + 127) / 128;

    // CSR build (once per call, reused by all 3 layers)
    k_zero_deg<<<ZB, 256>>>();
    k_count<<<EB, 256>>>(dst);
    k_scan1<<<NCHS, 1024>>>();
    k_scan2<<<1, 128>>>();
    k_scan3<<<ZB, 256>>>();
    k_fill<<<EB, 256>>>(src, dst);

    // layer 0
    k_aggregate<<<AGG_B, 256>>>(BUF_EXT, feat);
    k_gemm<256, 128, 128, 128, 16, 8, 8, true, true>
        <<<GEMM_B, 256>>>(BUF_EXT, feat, Ws0, Wn0, bs0, bn0, BUF_A, nullptr, N_NODES);
    // layer 1
    k_aggregate<<<AGG_B, 256>>>(BUF_A, nullptr);
    k_gemm<256, 128, 128, 128, 16, 8, 8, true, true>
        <<<GEMM_B, 256>>>(BUF_A, nullptr, Ws1, Wn1, bs1, bn1, BUF_B, nullptr, N_NODES);
    // layer 2 (no relu)
    k_aggregate<<<AGG_B, 256>>>(BUF_B, nullptr);
    k_gemm<256, 128, 128, 128, 16, 8, 8, true, false>
        <<<GEMM_B, 256>>>(BUF_B, nullptr, Ws2, Wn2, bs2, bn2, BUF_A, nullptr, N_NODES);
    // final projection: [100K,128] @ [128,64] + b
    k_gemm<128, 64, 128, 64, 16, 8, 4, false, false>
        <<<GEMM_B, 256>>>(BUF_A, nullptr, Wout, Wout, bout, bout, BUF_EXT, out, N_NODES);
}

// round 12
// speedup vs baseline: 1.9099x; 1.9099x over previous
#include <cuda_runtime.h>
#include <cuda_bf16.h>
#include <cstdint>
#include <cstddef>

#define N_NODES 100000
#define N_EDGES 600000
#define FEAT    128
#define NCHSC   ((N_NODES + 1023) / 1024)   // scan chunks: 98

// ---------------- scratch (device globals; no allocation allowed) ----------
__device__ __align__(128) float g_bufA[(size_t)N_NODES * FEAT];
__device__ __align__(128) float g_bufB[(size_t)N_NODES * FEAT];
__device__ __align__(128) float g_hn  [(size_t)N_NODES * FEAT];
__device__ int g_deg[N_NODES];
__device__ int g_rowptr[N_NODES + 1];
__device__ int g_cursor[N_NODES];
__device__ int g_csr[N_EDGES];
__device__ int g_blocksum[NCHSC];
__device__ int g_blockoff[NCHSC];
// pre-split weights, bf16 hi/lo, layout [mat][chunk][n][k16] (identity index)
// 6 layer mats (128n) then wout (64n) at offset 98304
#define WOUT_OFF 98304
__device__ __align__(16) __nv_bfloat16 g_wh[98304 + 8192];
__device__ __align__(16) __nv_bfloat16 g_wl[98304 + 8192];

#define BUF_EXT 0
#define BUF_A   1
#define BUF_B   2

__device__ __forceinline__ const float* sel_src(int sel, const float* ext) {
    if (sel == BUF_A) return g_bufA;
    if (sel == BUF_B) return g_bufB;
    return ext;
}
__device__ __forceinline__ float* sel_dst(int sel, float* ext) {
    if (sel == BUF_A) return g_bufA;
    if (sel == BUF_B) return g_bufB;
    return ext;
}

// ---------------- mma.sync m16n8k16 bf16 (sm_80+ portable) -----------------
__device__ __forceinline__ void mma16816(float* d, const uint32_t* a,
                                         const uint32_t* b) {
    asm volatile(
        "mma.sync.aligned.m16n8k16.row.col.f32.bf16.bf16.f32 "
        "{%0,%1,%2,%3}, {%4,%5,%6,%7}, {%8,%9}, {%0,%1,%2,%3};"
        : "+f"(d[0]), "+f"(d[1]), "+f"(d[2]), "+f"(d[3])
        : "r"(a[0]), "r"(a[1]), "r"(a[2]), "r"(a[3]), "r"(b[0]), "r"(b[1]));
}

// ---------------- CSR construction ----------------------------------------
__global__ void k_zero_deg() {
    int i = blockIdx.x * blockDim.x + threadIdx.x;
    if (i < N_NODES) g_deg[i] = 0;
}
__global__ void k_count(const int* __restrict__ dst) {
    int e = blockIdx.x * blockDim.x + threadIdx.x;
    if (e < N_EDGES) atomicAdd(&g_deg[dst[e]], 1);
}
__global__ __launch_bounds__(1024) void k_scan1() {
    __shared__ int sh[1024];
    int tid = threadIdx.x;
    int i = blockIdx.x * 1024 + tid;
    int v = (i < N_NODES) ? g_deg[i] : 0;
    sh[tid] = v;
    __syncthreads();
#pragma unroll
    for (int off = 1; off < 1024; off <<= 1) {
        int t = (tid >= off) ? sh[tid - off] : 0;
        __syncthreads();
        sh[tid] += t;
        __syncthreads();
    }
    if (i < N_NODES) g_rowptr[i] = sh[tid] - v;
    if (tid == 1023) g_blocksum[blockIdx.x] = sh[1023];
}
__global__ void k_scan2() {
    __shared__ int sh[128];
    int tid = threadIdx.x;
    int v = (tid < NCHSC) ? g_blocksum[tid] : 0;
    sh[tid] = v;
    __syncthreads();
#pragma unroll
    for (int off = 1; off < 128; off <<= 1) {
        int t = (tid >= off) ? sh[tid - off] : 0;
        __syncthreads();
        sh[tid] += t;
        __syncthreads();
    }
    if (tid < NCHSC) g_blockoff[tid] = sh[tid] - v;
    if (tid == NCHSC - 1) g_rowptr[N_NODES] = sh[tid];
}
__global__ void k_scan3() {
    int i = blockIdx.x * blockDim.x + threadIdx.x;
    if (i < N_NODES) {
        int r = g_rowptr[i] + g_blockoff[i >> 10];
        g_rowptr[i] = r;
        g_cursor[i] = r;
    }
}
__global__ void k_fill(const int* __restrict__ src, const int* __restrict__ dst) {
    int e = blockIdx.x * blockDim.x + threadIdx.x;
    if (e < N_EDGES) {
        int p = atomicAdd(&g_cursor[dst[e]], 1);
        g_csr[p] = src[e];
    }
}

// ---------------- neighbor mean aggregation (warp per node) ----------------
__global__ void k_aggregate(int h_sel, const float* __restrict__ h_ext) {
    const float* __restrict__ h = sel_src(h_sel, h_ext);
    int node = (blockIdx.x * blockDim.x + threadIdx.x) >> 5;
    if (node >= N_NODES) return;
    int lane = threadIdx.x & 31;
    int beg = g_rowptr[node], end = g_rowptr[node + 1];
    float4 acc = make_float4(0.f, 0.f, 0.f, 0.f);
    for (int e = beg; e < end; e++) {
        int s = g_csr[e];
        float4 v = ((const float4*)(h + (size_t)s * FEAT))[lane];
        acc.x += v.x; acc.y += v.y; acc.z += v.z; acc.w += v.w;
    }
    float inv = 1.0f / fmaxf((float)(end - beg), 1.0f);
    acc.x *= inv; acc.y *= inv; acc.z *= inv; acc.w *= inv;
    ((float4*)(g_hn + (size_t)node * FEAT))[lane] = acc;
}

// ---------------- weight prep: fp32 -> bf16 hi/lo, [mat][ch][n][k16] -------
__global__ void k_prep_w(const float* W0, const float* W1, const float* W2,
                         const float* W3, const float* W4, const float* W5,
                         const float* Wout) {
    int idx = blockIdx.x * blockDim.x + threadIdx.x;
    float x;
    if (idx < WOUT_OFF) {
        int mat = idx >> 14;          // /16384
        int r = idx & 16383;
        int ch = r >> 11;             // /2048
        int t = r & 2047;
        int n = t >> 4, kl = t & 15;
        const float* W = mat == 0 ? W0 : mat == 1 ? W1 : mat == 2 ? W2
                       : mat == 3 ? W3 : mat == 4 ? W4 : W5;
        x = W[(ch * 16 + kl) * 128 + n];
    } else if (idx < WOUT_OFF + 8192) {
        int r = idx - WOUT_OFF;
        int ch = r >> 10;
        int t = r & 1023;
        int n = t >> 4, kl = t & 15;
        x = Wout[(ch * 16 + kl) * 64 + n];
    } else {
        return;
    }
    __nv_bfloat16 h = __float2bfloat16(x);
    __nv_bfloat16 l = __float2bfloat16(x - __bfloat162float(h));
    g_wh[idx] = h;
    g_wl[idx] = l;
}

// ---------------- mma.sync split-bf16 GEMM ---------------------------------
// C[M,BN] = act( A1@W1 (+ hn@W2) + bias1 (+ bias2) ), K=128/mat, k16 chunks.
template <int NCH, int BN, bool DUAL, bool RELU>
__global__ __launch_bounds__(256)
void k_gemm_mma(int a_sel, const float* __restrict__ A_ext, int woff0,
                const float* __restrict__ bias1, const float* __restrict__ bias2,
                int c_sel, float* __restrict__ C_ext, int M) {
    constexpr int NTT = BN / 16;        // n8-tiles per warp (warp covers BN/2)
    constexpr int BCH = BN * 16;        // bf16 elems per weight chunk
    constexpr int PAD = 24;             // smem row stride in bf16 (48B): conflict-free

    __shared__ __align__(16) __nv_bfloat16 Ah[2][128 * PAD];
    __shared__ __align__(16) __nv_bfloat16 Al[2][128 * PAD];
    __shared__ __align__(16) __nv_bfloat16 Bh[2][BN * PAD];
    __shared__ __align__(16) __nv_bfloat16 Bl[2][BN * PAD];

    const int tid = threadIdx.x, lane = tid & 31, wid = tid >> 5;
    const int wm = wid >> 1, wn = wid & 1;
    const int g = lane >> 2, tq = lane & 3;
    const int row0 = blockIdx.x * 128;
    const float* __restrict__ A1 = sel_src(a_sel, A_ext);
    float* __restrict__ C = sel_dst(c_sel, C_ext);

    float acc[2][NTT][4];
#pragma unroll
    for (int mt = 0; mt < 2; mt++)
#pragma unroll
        for (int nt = 0; nt < NTT; nt++)
#pragma unroll
            for (int q = 0; q < 4; q++) acc[mt][nt][q] = 0.f;

    const int arow = tid >> 1, ahalf = tid & 1;
    const bool avalid = (row0 + arow) < M;
    float4 ra0, ra1;
    uint4 rbh, rbl;

    auto fetch = [&](int it) {
        const float* A = (!DUAL || it < NCH / 2) ? A1 : (const float*)g_hn;
        const int ch = DUAL ? (it & (NCH / 2 - 1)) : it;
        const float* ap = A + (size_t)(row0 + arow) * FEAT + ch * 16 + ahalf * 8;
        ra0 = avalid ? *(const float4*)ap : make_float4(0.f, 0.f, 0.f, 0.f);
        ra1 = avalid ? *(const float4*)(ap + 4) : make_float4(0.f, 0.f, 0.f, 0.f);
        const int woff = woff0 + ((DUAL && it >= NCH / 2) ? 16384 : 0) + ch * BCH;
        if (BN == 128 || tid < BCH / 8) {
            rbh = ((const uint4*)(g_wh + woff))[tid];
            rbl = ((const uint4*)(g_wl + woff))[tid];
        }
    };
    auto stash = [&](int s) {
        float xs[8] = {ra0.x, ra0.y, ra0.z, ra0.w, ra1.x, ra1.y, ra1.z, ra1.w};
        union { unsigned short u[8]; uint4 v; } hs, ls;
#pragma unroll
        for (int i = 0; i < 8; i++) {
            __nv_bfloat16 h = __float2bfloat16(xs[i]);
            __nv_bfloat16 l = __float2bfloat16(xs[i] - __bfloat162float(h));
            hs.u[i] = __bfloat16_as_ushort(h);
            ls.u[i] = __bfloat16_as_ushort(l);
        }
        *(uint4*)&Ah[s][arow * PAD + ahalf * 8] = hs.v;
        *(uint4*)&Al[s][arow * PAD + ahalf * 8] = ls.v;
        if (BN == 128 || tid < BCH / 8) {
            int n = tid >> 1, half = tid & 1;
            *(uint4*)&Bh[s][n * PAD + half * 8] = rbh;
            *(uint4*)&Bl[s][n * PAD + half * 8] = rbl;
        }
    };

    fetch(0);
    stash(0);
    __syncthreads();

#pragma unroll 1
    for (int it = 0; it < NCH; it++) {
        const int s = it & 1;
        if (it + 1 < NCH) fetch(it + 1);

        // A fragments (hi & lo) for both m16 tiles of this warp
        uint32_t ah[2][4], al[2][4];
#pragma unroll
        for (int mt = 0; mt < 2; mt++) {
            const int base = wm * 32 + mt * 16;
            ah[mt][0] = *(const uint32_t*)&Ah[s][(base + g) * PAD + tq * 2];
            ah[mt][1] = *(const uint32_t*)&Ah[s][(base + g + 8) * PAD + tq * 2];
            ah[mt][2] = *(const uint32_t*)&Ah[s][(base + g) * PAD + tq * 2 + 8];
            ah[mt][3] = *(const uint32_t*)&Ah[s][(base + g + 8) * PAD + tq * 2 + 8];
            al[mt][0] = *(const uint32_t*)&Al[s][(base + g) * PAD + tq * 2];
            al[mt][1] = *(const uint32_t*)&Al[s][(base + g + 8) * PAD + tq * 2];
            al[mt][2] = *(const uint32_t*)&Al[s][(base + g) * PAD + tq * 2 + 8];
            al[mt][3] = *(const uint32_t*)&Al[s][(base + g + 8) * PAD + tq * 2 + 8];
        }
#pragma unroll
        for (int nt = 0; nt < NTT; nt++) {
            const int n = wn * (BN / 2) + nt * 8 + g;
            uint32_t bh[2], bl[2];
            bh[0] = *(const uint32_t*)&Bh[s][n * PAD + tq * 2];
            bh[1] = *(const uint32_t*)&Bh[s][n * PAD + tq * 2 + 8];
            bl[0] = *(const uint32_t*)&Bl[s][n * PAD + tq * 2];
            bl[1] = *(const uint32_t*)&Bl[s][n * PAD + tq * 2 + 8];
#pragma unroll
            for (int mt = 0; mt < 2; mt++) {
                mma16816(acc[mt][nt], ah[mt], bh);   // AhWh
                mma16816(acc[mt][nt], ah[mt], bl);   // AhWl
                mma16816(acc[mt][nt], al[mt], bh);   // AlWh
            }
        }
        if (it + 1 < NCH) {
            stash((it + 1) & 1);
            __syncthreads();
        }
    }

    // epilogue: bias (+relu) -> C
#pragma unroll
    for (int mt = 0; mt < 2; mt++) {
        const int r0 = row0 + wm * 32 + mt * 16 + g;
#pragma unroll
        for (int nt = 0; nt < NTT; nt++) {
            const int c = wn * (BN / 2) + nt * 8 + tq * 2;
            const float b0 = bias1[c]     + (DUAL ? bias2[c]     : 0.f);
            const float b1 = bias1[c + 1] + (DUAL ? bias2[c + 1] : 0.f);
            float x0 = acc[mt][nt][0] + b0, x1 = acc[mt][nt][1] + b1;
            float x2 = acc[mt][nt][2] + b0, x3 = acc[mt][nt][3] + b1;
            if (RELU) {
                x0 = fmaxf(x0, 0.f); x1 = fmaxf(x1, 0.f);
                x2 = fmaxf(x2, 0.f); x3 = fmaxf(x3, 0.f);
            }
            if (r0 < M)
                *(float2*)(C + (size_t)r0 * BN + c) = make_float2(x0, x1);
            if (r0 + 8 < M)
                *(float2*)(C + (size_t)(r0 + 8) * BN + c) = make_float2(x2, x3);
        }
    }
}

// ---------------- launch ----------------------------------------------------
extern "C" void kernel_launch(void* const* d_in, const int* in_sizes, int n_in,
                              void* d_out, int out_size) {
    const float* feat = (const float*)d_in[0];
    const int*   src  = (const int*)d_in[1];
    const int*   dst  = (const int*)d_in[2];
    const float* Ws0 = (const float*)d_in[3];  const float* bs0 = (const float*)d_in[4];
    const float* Wn0 = (const float*)d_in[5];  const float* bn0 = (const float*)d_in[6];
    const float* Ws1 = (const float*)d_in[7];  const float* bs1 = (const float*)d_in[8];
    const float* Wn1 = (const float*)d_in[9];  const float* bn1 = (const float*)d_in[10];
    const float* Ws2 = (const float*)d_in[11]; const float* bs2 = (const float*)d_in[12];
    const float* Wn2 = (const float*)d_in[13]; const float* bn2 = (const float*)d_in[14];
    const float* Wout = (const float*)d_in[15]; const float* bout = (const float*)d_in[16];
    float* out = (float*)d_out;

    const int ZB = (N_NODES + 255) / 256;
    const int EB = (N_EDGES + 255) / 256;
    const int AGG_B  = (N_NODES + 7) / 8;
    const int GEMM_B = (N_NODES + 127) / 128;     // 782
    const int PREP_B = (WOUT_OFF + 8192 + 255) / 256;

    // weight prep + CSR build
    k_prep_w<<<PREP_B, 256>>>(Ws0, Wn0, Ws1, Wn1, Ws2, Wn2, Wout);
    k_zero_deg<<<ZB, 256>>>();
    k_count<<<EB, 256>>>(dst);
    k_scan1<<<NCHSC, 1024>>>();
    k_scan2<<<1, 128>>>();
    k_scan3<<<ZB, 256>>>();
    k_fill<<<EB, 256>>>(src, dst);

    // layer 0: mats 0 (self), 1 (neigh)
    k_aggregate<<<AGG_B, 256>>>(BUF_EXT, feat);
    k_gemm_mma<16, 128, true, true><<<GEMM_B, 256>>>(
        BUF_EXT, feat, 0 * 16384, bs0, bn0, BUF_A, nullptr, N_NODES);
    // layer 1: mats 2, 3
    k_aggregate<<<AGG_B, 256>>>(BUF_A, nullptr);
    k_gemm_mma<16, 128, true, true><<<GEMM_B, 256>>>(
        BUF_A, nullptr, 2 * 16384, bs1, bn1, BUF_B, nullptr, N_NODES);
    // layer 2: mats 4, 5 (no relu)
    k_aggregate<<<AGG_B, 256>>>(BUF_B, nullptr);
    k_gemm_mma<16, 128, true, false><<<GEMM_B, 256>>>(
        BUF_B, nullptr, 4 * 16384, bs2, bn2, BUF_A, nullptr, N_NODES);
    // final projection [100K,128]@[128,64]+b
    k_gemm_mma<8, 64, false, false><<<GEMM_B, 256>>>(
        BUF_A, nullptr, WOUT_OFF, bout, bout, BUF_EXT, out, N_NODES);
}